// round 15
// baseline (speedup 1.0000x reference)
#include <cuda_runtime.h>
#include <cuda_fp16.h>
#include <stdint.h>
#include <string.h>

#define T_TOK 2048
#define H_DIM 2048
#define I_DIM 1408
#define NE    8
#define GS    128
#define BM    128
#define BK    64
#define LDSW  72                        // fp16 smem row stride in halves (144B)

// ---- gemm1 (int32 B) smem layout ----
#define G1_A_ST    18432                // A stage: 128 rows x 144 B
#define G1_BROW    272                  // Bint row stride bytes (64 ints + 4 pad)
#define G1_B_ST    (128 * G1_BROW)      // 34816
#define G1_STAGE   (G1_A_ST + G1_B_ST)  // 53248
#define G1_SMEM    (2 * G1_STAGE)       // 106496 -> 2 CTAs/SM

// ---- gemm2 (R12 config) smem ----
#define A_OFF_B   (128 * LDSW * 2)
#define STAGE_B   (2 * 128 * LDSW * 2)
#define NSTAGE    3
#define G2_SMEM   (NSTAGE * STAGE_B)    // 110592

// prep grid partition (convert_x + zero only now)
#define NB_X    2048
#define NB_Z    4096

// ---- persistent device scratch ----
__device__ int    g_cnt[NE];
__device__ int    g_tok[NE * T_TOK];
__device__ float  g_rw [NE * T_TOK];
__device__ __half g_x  [(size_t)T_TOK * H_DIM];
__device__ __half g_act[(size_t)NE * T_TOK * I_DIM];
__device__ __half g_wd [(size_t)NE * H_DIM * I_DIM];      // fp16 down weights (hidden dequant)

// ---------------- helpers ----------------
__device__ __forceinline__ uint32_t h2u(__half2 h) { uint32_t u; memcpy(&u, &h, 4); return u; }
__device__ __forceinline__ uint32_t smem_u32(const void* p) {
    uint32_t a;
    asm("{ .reg .u64 t; cvta.to.shared.u64 t, %1; cvt.u32.u64 %0, t; }" : "=r"(a) : "l"(p));
    return a;
}
__device__ __forceinline__ void ldm_x4(uint32_t* r, uint32_t addr) {
    asm volatile("ldmatrix.sync.aligned.m8n8.x4.shared.b16 {%0,%1,%2,%3}, [%4];"
        : "=r"(r[0]), "=r"(r[1]), "=r"(r[2]), "=r"(r[3]) : "r"(addr));
}
__device__ __forceinline__ void mma16816(float* d, const uint32_t* a, const uint32_t* b) {
    asm volatile("mma.sync.aligned.m16n8k16.row.col.f32.f16.f16.f32 "
        "{%0,%1,%2,%3}, {%4,%5,%6,%7}, {%8,%9}, {%0,%1,%2,%3};"
        : "+f"(d[0]), "+f"(d[1]), "+f"(d[2]), "+f"(d[3])
        : "r"(a[0]), "r"(a[1]), "r"(a[2]), "r"(a[3]), "r"(b[0]), "r"(b[1]));
}
__device__ __forceinline__ void cp16(uint32_t dst, const void* src) {
    asm volatile("cp.async.cg.shared.global [%0], [%1], 16;" :: "r"(dst), "l"(src));
}
#define CP_COMMIT()  asm volatile("cp.async.commit_group;")
#define CP_WAIT(n)   asm volatile("cp.async.wait_group %0;" :: "n"(n))

// convert 2 int32 weights -> packed f16x2 with scale (exactly round((q-8)*sv))
__device__ __forceinline__ uint32_t dq2(int2 q, float sv, float ns) {
    float f0 = fmaf((float)q.x, sv, ns);
    float f1 = fmaf((float)q.y, sv, ns);
    return h2u(__floats2half2_rn(f0, f1));
}

// ---------------- L0: routing (single block) ----------------
__global__ __launch_bounds__(1024) void route_kernel(const float* __restrict__ logits) {
    __shared__ int scnt[NE];
    const int tid = threadIdx.x;
    if (tid < NE) scnt[tid] = 0;
    __syncthreads();
    for (int t = tid; t < T_TOK; t += 1024) {
        float v[NE];
#pragma unroll
        for (int e = 0; e < NE; ++e) v[e] = logits[t * NE + e];
        int i0 = 0;
#pragma unroll
        for (int e = 1; e < NE; ++e) if (v[e] > v[i0]) i0 = e;
        int i1 = (i0 == 0) ? 1 : 0;
#pragma unroll
        for (int e = 0; e < NE; ++e) if (e != i0 && v[e] > v[i1]) i1 = e;
        float ex = __expf(v[i1] - v[i0]);
        float w0 = 1.0f / (1.0f + ex);
        float w1 = ex * w0;
        int p0 = atomicAdd(&scnt[i0], 1);
        g_tok[i0 * T_TOK + p0] = t;  g_rw[i0 * T_TOK + p0] = w0;
        int p1 = atomicAdd(&scnt[i1], 1);
        g_tok[i1 * T_TOK + p1] = t;  g_rw[i1 * T_TOK + p1] = w1;
    }
    __syncthreads();
    if (tid < NE) g_cnt[tid] = scnt[tid];
}

// ---------------- L1: prep = convert_x | zero out ----------------
__global__ void prep_kernel(const float* __restrict__ x, float* __restrict__ out) {
    const int bid = blockIdx.x;
    if (bid < NB_X) {
        size_t i = ((size_t)bid * 256 + threadIdx.x) * 8;
        float4 a = *(const float4*)(x + i);
        float4 b = *(const float4*)(x + i + 4);
        uint4 o;
        o.x = h2u(__floats2half2_rn(a.x, a.y));
        o.y = h2u(__floats2half2_rn(a.z, a.w));
        o.z = h2u(__floats2half2_rn(b.x, b.y));
        o.w = h2u(__floats2half2_rn(b.z, b.w));
        *(uint4*)(g_x + i) = o;
    } else {
        size_t i = ((size_t)(bid - NB_X) * 256 + threadIdx.x) * 4;
        *(float4*)(out + i) = make_float4(0.f, 0.f, 0.f, 0.f);
    }
}

// =================================================================
// GEMM1: g_x @ W_gate/up with IN-REGISTER int4 dequant.
// B loaded as raw int32 into smem; B fragments built by LDS.64 +
// fmaf + cvt (no ldmatrix for B). A path unchanged (fp16 + ldmatrix).
// BM=128, tile = 64 gate + 64 up rows -> 64 act features, BK=64,
// 2-stage cp.async. blockIdx.y==0 = hidden dequant_dn slice.
// grid (16, 23, 8).
// =================================================================
__global__ __launch_bounds__(256, 2) void gemm1_kernel(
    const int* __restrict__ qgu, const float* __restrict__ sgu,
    const int* __restrict__ qd,  const float* __restrict__ sd)
{
    const int e = blockIdx.z;

    if (blockIdx.y == 0) {
        // ---- hidden dequant_dn slice: 128 CTAs total ----
        const int cta = blockIdx.z * 16 + blockIdx.x;
        const int nthreads = 128 * 256;
        const int total = NE * H_DIM * (I_DIM / 16);
        for (int gid = cta * 256 + threadIdx.x; gid < total; gid += nthreads) {
            int row = gid / 88;
            int kc  = (gid - row * 88) << 4;
            const int4* src = (const int4*)(qd + (size_t)row * I_DIM + kc);
            float sc = sd[row * (I_DIM / GS) + (kc >> 7)];
            uint32_t o[8];
#pragma unroll
            for (int j = 0; j < 4; ++j) {
                int4 v = src[j];
                o[j * 2 + 0] = h2u(__floats2half2_rn(sc * (float)(v.x - 8), sc * (float)(v.y - 8)));
                o[j * 2 + 1] = h2u(__floats2half2_rn(sc * (float)(v.z - 8), sc * (float)(v.w - 8)));
            }
            uint4* dst = (uint4*)(g_wd + (size_t)row * I_DIM + kc);
            dst[0] = make_uint4(o[0], o[1], o[2], o[3]);
            dst[1] = make_uint4(o[4], o[5], o[6], o[7]);
        }
        return;
    }

    const int cnt = g_cnt[e];
    const int m0  = blockIdx.x * BM;
    if (m0 >= cnt) return;
    const int n0  = (blockIdx.y - 1) * 64;

    extern __shared__ char smem[];
    const uint32_t sbase = smem_u32(smem);

    const int tid = threadIdx.x, lane = tid & 31, wid = tid >> 5;
    const int warp_m = wid & 3, warp_n = wid >> 2;

    // ---- A loader: 128 rows x 128B/slab (fp16), 2 thr/row, 4 cp16 ----
    const int arow = tid >> 1, aseg = tid & 1;
    int am = m0 + arow; if (am >= cnt) am = cnt - 1;
    const __half* asrc = g_x + (size_t)g_tok[e * T_TOK + am] * H_DIM + aseg * 32;
    const uint32_t adst = (uint32_t)(arow * 144 + aseg * 64);

    // ---- B loader: 128 rows x 256B/slab (int32), 2 thr/row, 8 cp16 ----
    const int brw = tid >> 1, bseg = tid & 1;
    const int grow = (brw < 64) ? (n0 + brw) : (I_DIM + n0 + brw - 64);
    const int* bsrc = qgu + ((size_t)e * 2 * I_DIM + grow) * H_DIM + bseg * 32;
    const uint32_t bdst = (uint32_t)(G1_A_ST + brw * G1_BROW + bseg * 128);

    float accg[2][4][4], accu[2][4][4];
#pragma unroll
    for (int a = 0; a < 2; ++a)
#pragma unroll
        for (int b = 0; b < 4; ++b)
#pragma unroll
            for (int c = 0; c < 4; ++c) { accg[a][b][c] = 0.f; accu[a][b][c] = 0.f; }

    // A ldmatrix offsets
    const int arow0 = warp_m * 32 + (lane & 15);
    const int acol  = (lane >> 4) * 8;
    const uint32_t aoff0 = (uint32_t)((arow0 * LDSW + acol) * 2);
    const uint32_t aoff1 = (uint32_t)(((arow0 + 16) * LDSW + acol) * 2);

    // B fragment coords: frag j covers tile rows warp_n*32 + j*8 + (lane>>2)
    const int fr = (lane >> 2);
    const int fk = (lane & 3) * 2;          // int index within k16
    uint32_t bfoff[4];                       // byte offset of gate frag j (k base added later)
#pragma unroll
    for (int j = 0; j < 4; ++j)
        bfoff[j] = (uint32_t)(G1_A_ST + (warp_n * 32 + j * 8 + fr) * G1_BROW + fk * 4);
    const uint32_t upd = (uint32_t)(64 * G1_BROW);   // up rows at +64

    // scale row pointers (global)
    const float* scp[4];
#pragma unroll
    for (int j = 0; j < 4; ++j)
        scp[j] = sgu + ((size_t)e * 2 * I_DIM + n0 + warp_n * 32 + j * 8 + fr) * (H_DIM / GS);
    const size_t up_sc = (size_t)I_DIM * (H_DIM / GS);

    // prologue: slab 0 -> stage 0
#pragma unroll
    for (int c = 0; c < 4; ++c) cp16(sbase + adst + c * 16, asrc + c * 8);
#pragma unroll
    for (int c = 0; c < 8; ++c) cp16(sbase + bdst + c * 16, bsrc + c * 4);
    CP_COMMIT();

    float sg[4], su[4];
    const int S = H_DIM / BK;   // 32
    for (int s = 0; s < S; ++s) {
        if ((s & 1) == 0) {     // group boundary: refresh scales (L1-hit LDG)
            const int g = s >> 1;
#pragma unroll
            for (int j = 0; j < 4; ++j) { sg[j] = scp[j][g]; su[j] = scp[j][up_sc + g]; }
        }
        if (s + 1 < S) {
            const uint32_t stg = (uint32_t)(((s + 1) & 1) * G1_STAGE);
            const int kb = (s + 1) * BK;
#pragma unroll
            for (int c = 0; c < 4; ++c) cp16(sbase + stg + adst + c * 16, asrc + kb + c * 8);
#pragma unroll
            for (int c = 0; c < 8; ++c) cp16(sbase + stg + bdst + c * 16, bsrc + kb + c * 4);
            CP_COMMIT();
            CP_WAIT(1);
        } else {
            CP_WAIT(0);
        }
        __syncthreads();

        const uint32_t stg = (uint32_t)((s & 1) * G1_STAGE);
        const char* sB = smem + stg;
        const uint32_t sa = sbase + stg;
#pragma unroll
        for (int ks = 0; ks < 4; ++ks) {
            uint32_t A[2][4];
            ldm_x4(A[0], sa + aoff0 + (uint32_t)(ks * 32));
            ldm_x4(A[1], sa + aoff1 + (uint32_t)(ks * 32));
            const uint32_t kadd = (uint32_t)(ks * 64);   // 16 ints = 64 B
#pragma unroll
            for (int j = 0; j < 4; ++j) {
                const char* pg = sB + bfoff[j] + kadd;
                const float nsg = -8.0f * sg[j];
                uint32_t Bg[2];
                Bg[0] = dq2(*(const int2*)(pg),      sg[j], nsg);
                Bg[1] = dq2(*(const int2*)(pg + 32), sg[j], nsg);
                mma16816(accg[0][j], A[0], Bg);
                mma16816(accg[1][j], A[1], Bg);
                const char* pu = pg + upd;
                const float nsu = -8.0f * su[j];
                uint32_t Bu[2];
                Bu[0] = dq2(*(const int2*)(pu),      su[j], nsu);
                Bu[1] = dq2(*(const int2*)(pu + 32), su[j], nsu);
                mma16816(accu[0][j], A[0], Bu);
                mma16816(accu[1][j], A[1], Bu);
            }
        }
        __syncthreads();
    }

    // ---- epilogue: SwiGLU -> g_act ----
#pragma unroll
    for (int mf = 0; mf < 2; ++mf) {
#pragma unroll
        for (int hr = 0; hr < 2; ++hr) {
            const int m = m0 + warp_m * 32 + mf * 16 + (lane >> 2) + hr * 8;
            if (m >= cnt) continue;
            __half* arowp = g_act + ((size_t)e * T_TOK + m) * I_DIM;
#pragma unroll
            for (int nf = 0; nf < 4; ++nf) {
                const int c = n0 + warp_n * 32 + nf * 8 + (lane & 3) * 2;
                const float g0 = accg[mf][nf][hr * 2 + 0];
                const float g1 = accg[mf][nf][hr * 2 + 1];
                const float u0 = accu[mf][nf][hr * 2 + 0];
                const float u1 = accu[mf][nf][hr * 2 + 1];
                const float a0 = g0 / (1.0f + __expf(-g0)) * u0;
                const float a1 = g1 / (1.0f + __expf(-g1)) * u1;
                *(__half2*)&arowp[c] = __floats2half2_rn(a0, a1);
            }
        }
    }
}

// =================================================================
// GEMM2 (unchanged R12): g_act @ g_wd^T, BM=128, BN=128, BK=64,
// 3-stage cp.async, route-weighted atomicAdd into out.
// =================================================================
__global__ __launch_bounds__(256, 2) void gemm2_kernel(float* __restrict__ out) {
    const int e   = blockIdx.z;
    const int cnt = g_cnt[e];
    const int m0  = blockIdx.x * BM;
    if (m0 >= cnt) return;
    const int n0  = blockIdx.y * 128;

    extern __shared__ char smemc[];
    __half* smem = (__half*)smemc;
    const uint32_t sbase = smem_u32(smem);

    const int tid = threadIdx.x, lane = tid & 31, wid = tid >> 5;
    const int warp_m = wid & 3, warp_n = wid >> 2;

    const int rb = tid >> 3, ch = tid & 7;
    const __half* asrc[4];
    const __half* bsrc[4];
    uint32_t adst[4], bdst[4];
#pragma unroll
    for (int p = 0; p < 4; ++p) {
        int r = rb + p * 32;
        int m = m0 + r; if (m >= cnt) m = cnt - 1;
        asrc[p] = g_act + ((size_t)e * T_TOK + m) * I_DIM + ch * 8;
        bsrc[p] = g_wd + ((size_t)e * H_DIM + n0 + r) * I_DIM + ch * 8;
        adst[p] = (uint32_t)((r * LDSW + ch * 8) * 2);
        bdst[p] = adst[p] + A_OFF_B;
    }

    float acc[2][8][4];
#pragma unroll
    for (int a = 0; a < 2; ++a)
#pragma unroll
        for (int b = 0; b < 8; ++b)
#pragma unroll
            for (int c = 0; c < 4; ++c) acc[a][b][c] = 0.f;

    const int arow0 = warp_m * 32 + (lane & 15);
    const int acol  = (lane >> 4) * 8;
    const int brow  = (lane & 7) + ((lane >> 4) << 3);
    const int bcol  = ((lane >> 3) & 1) * 8;

    const int S = I_DIM / BK;   // 22
#pragma unroll
    for (int s = 0; s < 2; ++s) {
        const uint32_t stg = sbase + (uint32_t)(s * STAGE_B);
        const int kb = s * BK;
#pragma unroll
        for (int p = 0; p < 4; ++p) {
            cp16(stg + adst[p], asrc[p] + kb);
            cp16(stg + bdst[p], bsrc[p] + kb);
        }
        CP_COMMIT();
    }

    int buf = 0;
    for (int s = 0; s < S; ++s) {
        CP_WAIT(1);
        __syncthreads();
        if (s + 2 < S) {
            int nb = buf + 2; if (nb >= NSTAGE) nb -= NSTAGE;
            const uint32_t stg = sbase + (uint32_t)(nb * STAGE_B);
            const int kb = (s + 2) * BK;
#pragma unroll
            for (int p = 0; p < 4; ++p) {
                cp16(stg + adst[p], asrc[p] + kb);
                cp16(stg + bdst[p], bsrc[p] + kb);
            }
        }
        CP_COMMIT();

        const uint32_t sa = sbase + (uint32_t)(buf * STAGE_B);
        const uint32_t sb = sa + A_OFF_B;
#pragma unroll
        for (int ks = 0; ks < 4; ++ks) {
            const int kc = ks * 16;
            uint32_t A[2][4], B[4][4];
            ldm_x4(A[0], sa + (uint32_t)(((arow0     ) * LDSW + kc + acol) * 2));
            ldm_x4(A[1], sa + (uint32_t)(((arow0 + 16) * LDSW + kc + acol) * 2));
#pragma unroll
            for (int bb = 0; bb < 4; ++bb)
                ldm_x4(B[bb], sb + (uint32_t)(((warp_n * 64 + bb * 16 + brow) * LDSW + kc + bcol) * 2));
#pragma unroll
            for (int mf = 0; mf < 2; ++mf)
#pragma unroll
                for (int nf = 0; nf < 8; ++nf)
                    mma16816(acc[mf][nf], A[mf], &B[nf >> 1][(nf & 1) * 2]);
        }
        if (++buf == NSTAGE) buf = 0;
    }

#pragma unroll
    for (int mf = 0; mf < 2; ++mf) {
#pragma unroll
        for (int hr = 0; hr < 2; ++hr) {
            const int m = m0 + warp_m * 32 + mf * 16 + (lane >> 2) + hr * 8;
            if (m >= cnt) continue;
            const int   tok = g_tok[e * T_TOK + m];
            const float rw  = g_rw [e * T_TOK + m];
            float* orow = out + (size_t)tok * H_DIM;
#pragma unroll
            for (int nf = 0; nf < 8; ++nf) {
                const int c = n0 + warp_n * 64 + nf * 8 + (lane & 3) * 2;
                atomicAdd(&orow[c],     rw * acc[mf][nf][hr * 2 + 0]);
                atomicAdd(&orow[c + 1], rw * acc[mf][nf][hr * 2 + 1]);
            }
        }
    }
}

// ---------------------------------------------------------------
extern "C" void kernel_launch(void* const* d_in, const int* in_sizes, int n_in,
                              void* d_out, int out_size) {
    const float* logits = (const float*)d_in[0];
    const float* x      = (const float*)d_in[1];
    const int*   qgu    = (const int*)  d_in[2];
    const float* sgu    = (const float*)d_in[3];
    const int*   qd     = (const int*)  d_in[4];
    const float* sd     = (const float*)d_in[5];
    float* out = (float*)d_out;

    cudaFuncSetAttribute(gemm1_kernel, cudaFuncAttributeMaxDynamicSharedMemorySize, G1_SMEM);
    cudaFuncSetAttribute(gemm2_kernel, cudaFuncAttributeMaxDynamicSharedMemorySize, G2_SMEM);

    route_kernel<<<1, 1024>>>(logits);
    prep_kernel<<<NB_X + NB_Z, 256>>>(x, out);

    dim3 g1(T_TOK / BM, I_DIM / 64 + 1, NE);   // (16, 23, 8): y==0 = dequant_dn slice
    gemm1_kernel<<<g1, 256, G1_SMEM>>>(qgu, sgu, qd, sd);

    dim3 g2(T_TOK / BM, H_DIM / 128, NE);      // (16, 16, 8)
    gemm2_kernel<<<g2, 256, G2_SMEM>>>(out);
}

// round 16
// speedup vs baseline: 1.8896x; 1.8896x over previous
#include <cuda_runtime.h>
#include <cuda_fp16.h>
#include <stdint.h>
#include <string.h>

#define T_TOK 2048
#define H_DIM 2048
#define I_DIM 1408
#define NE    8
#define GS    128
#define BM    128
#define BK    64
#define LDSW  72                        // smem row stride in halves (144B)
#define A_OFF_B   (128 * LDSW * 2)      // B tile byte offset within a stage
#define STAGE_B   (2 * 128 * LDSW * 2)  // stage bytes (A + B tiles)
#define NSTAGE    3
#define SMEM_BYTES (NSTAGE * STAGE_B)   // 110592 B

#define N_PROD    128                   // producer CTAs (bids 0..127)
#define PROD_THREADS (N_PROD * 256)     // 32768

// ---- persistent device scratch ----
__device__ int    g_cnt[NE];
__device__ int    g_done[NE];           // producer progress flags
__device__ int    g_tok[NE * T_TOK];
__device__ float  g_rw [NE * T_TOK];
__device__ __half g_x  [(size_t)T_TOK * H_DIM];
__device__ __half g_act[(size_t)NE * T_TOK * I_DIM];
__device__ __half g_wgu[(size_t)NE * 2 * I_DIM * H_DIM];  // 92 MB fp16
__device__ __half g_wd [(size_t)NE * H_DIM * I_DIM];      // 46 MB fp16

// ---------------- helpers ----------------
__device__ __forceinline__ uint32_t h2u(__half2 h) { uint32_t u; memcpy(&u, &h, 4); return u; }
__device__ __forceinline__ uint32_t smem_u32(const void* p) {
    uint32_t a;
    asm("{ .reg .u64 t; cvta.to.shared.u64 t, %1; cvt.u32.u64 %0, t; }" : "=r"(a) : "l"(p));
    return a;
}
__device__ __forceinline__ void ldm_x4(uint32_t* r, uint32_t addr) {
    asm volatile("ldmatrix.sync.aligned.m8n8.x4.shared.b16 {%0,%1,%2,%3}, [%4];"
        : "=r"(r[0]), "=r"(r[1]), "=r"(r[2]), "=r"(r[3]) : "r"(addr));
}
__device__ __forceinline__ void mma16816(float* d, const uint32_t* a, const uint32_t* b) {
    asm volatile("mma.sync.aligned.m16n8k16.row.col.f32.f16.f16.f32 "
        "{%0,%1,%2,%3}, {%4,%5,%6,%7}, {%8,%9}, {%0,%1,%2,%3};"
        : "+f"(d[0]), "+f"(d[1]), "+f"(d[2]), "+f"(d[3])
        : "r"(a[0]), "r"(a[1]), "r"(a[2]), "r"(a[3]), "r"(b[0]), "r"(b[1]));
}
__device__ __forceinline__ void cp16(uint32_t dst, const void* src) {
    asm volatile("cp.async.cg.shared.global [%0], [%1], 16;" :: "r"(dst), "l"(src));
}
#define CP_COMMIT()  asm volatile("cp.async.commit_group;")
#define CP_WAIT(n)   asm volatile("cp.async.wait_group %0;" :: "n"(n))

// ---------------- L0: routing (single block) + flag reset ----------------
__global__ __launch_bounds__(1024) void route_kernel(const float* __restrict__ logits) {
    __shared__ int scnt[NE];
    const int tid = threadIdx.x;
    if (tid < NE) { scnt[tid] = 0; g_done[tid] = 0; }
    __syncthreads();
    for (int t = tid; t < T_TOK; t += 1024) {
        float v[NE];
#pragma unroll
        for (int e = 0; e < NE; ++e) v[e] = logits[t * NE + e];
        int i0 = 0;
#pragma unroll
        for (int e = 1; e < NE; ++e) if (v[e] > v[i0]) i0 = e;
        int i1 = (i0 == 0) ? 1 : 0;
#pragma unroll
        for (int e = 0; e < NE; ++e) if (e != i0 && v[e] > v[i1]) i1 = e;
        float ex = __expf(v[i1] - v[i0]);
        float w0 = 1.0f / (1.0f + ex);
        float w1 = ex * w0;
        int p0 = atomicAdd(&scnt[i0], 1);
        g_tok[i0 * T_TOK + p0] = t;  g_rw[i0 * T_TOK + p0] = w0;
        int p1 = atomicAdd(&scnt[i1], 1);
        g_tok[i1 * T_TOK + p1] = t;  g_rw[i1 * T_TOK + p1] = w1;
    }
    __syncthreads();
    if (tid < NE) g_cnt[tid] = scnt[tid];
}

// =================================================================
// FUSED kernel: producers (bid<128) + gemm1 consumers (bid>=128).
// Producers: convert_x -> gate_up dequant per expert (flag after each)
//            -> dequant_dn -> zero out.
// Consumers: spin on g_done[e]==128, then R14 gemm1 body.
// =================================================================
__global__ __launch_bounds__(256, 2) void fused1_kernel(
    const float* __restrict__ x,
    const int* __restrict__ qgu, const float* __restrict__ sgu,
    const int* __restrict__ qd,  const float* __restrict__ sd,
    float* __restrict__ out)
{
    const int bid = blockIdx.x;
    const int tid = threadIdx.x;

    if (bid < N_PROD) {
        // ================= PRODUCER =================
        const int gt = bid * 256 + tid;             // 0..32767

        // ---- convert_x: 524288 chunks of 8 floats, 16 iters ----
#pragma unroll 4
        for (int it = 0; it < 16; ++it) {
            size_t i = ((size_t)gt + (size_t)it * PROD_THREADS) * 8;
            float4 a = *(const float4*)(x + i);
            float4 b = *(const float4*)(x + i + 4);
            uint4 o;
            o.x = h2u(__floats2half2_rn(a.x, a.y));
            o.y = h2u(__floats2half2_rn(a.z, a.w));
            o.z = h2u(__floats2half2_rn(b.x, b.y));
            o.w = h2u(__floats2half2_rn(b.z, b.w));
            *(uint4*)(g_x + i) = o;
        }

        // ---- gate_up dequant, expert by expert (360448 chunks = 11 iters) ----
        for (int e = 0; e < NE; ++e) {
            for (int it = 0; it < 11; ++it) {
                int gid = gt + it * PROD_THREADS;
                int row = e * 2 * I_DIM + (gid >> 7);
                int kc  = (gid & 127) << 4;
                const int4* src = (const int4*)(qgu + (size_t)row * H_DIM + kc);
                float sc = sgu[row * (H_DIM / GS) + (kc >> 7)];
                uint32_t o[8];
#pragma unroll
                for (int j = 0; j < 4; ++j) {
                    int4 v = src[j];
                    o[j * 2 + 0] = h2u(__floats2half2_rn(sc * (float)(v.x - 8), sc * (float)(v.y - 8)));
                    o[j * 2 + 1] = h2u(__floats2half2_rn(sc * (float)(v.z - 8), sc * (float)(v.w - 8)));
                }
                uint4* dst = (uint4*)(g_wgu + (size_t)row * H_DIM + kc);
                dst[0] = make_uint4(o[0], o[1], o[2], o[3]);
                dst[1] = make_uint4(o[4], o[5], o[6], o[7]);
            }
            __syncthreads();
            __threadfence();
            if (tid == 0) atomicAdd(&g_done[e], 1);
        }

        // ---- dequant_dn: 1441792 chunks = 44 iters (consumed by gemm2 only) ----
        for (int it = 0; it < 44; ++it) {
            int gid = gt + it * PROD_THREADS;
            int row = gid / 88;
            int kc  = (gid - row * 88) << 4;
            const int4* src = (const int4*)(qd + (size_t)row * I_DIM + kc);
            float sc = sd[row * (I_DIM / GS) + (kc >> 7)];
            uint32_t o[8];
#pragma unroll
            for (int j = 0; j < 4; ++j) {
                int4 v = src[j];
                o[j * 2 + 0] = h2u(__floats2half2_rn(sc * (float)(v.x - 8), sc * (float)(v.y - 8)));
                o[j * 2 + 1] = h2u(__floats2half2_rn(sc * (float)(v.z - 8), sc * (float)(v.w - 8)));
            }
            uint4* dst = (uint4*)(g_wd + (size_t)row * I_DIM + kc);
            dst[0] = make_uint4(o[0], o[1], o[2], o[3]);
            dst[1] = make_uint4(o[4], o[5], o[6], o[7]);
        }

        // ---- zero out: 1048576 float4 = 32 iters ----
#pragma unroll 4
        for (int it = 0; it < 32; ++it) {
            size_t i = ((size_t)gt + (size_t)it * PROD_THREADS) * 4;
            *(float4*)(out + i) = make_float4(0.f, 0.f, 0.f, 0.f);
        }
        return;
    }

    // ================= GEMM1 CONSUMER =================
    const int idx   = bid - N_PROD;
    const int mtile = idx & 15;
    const int rest  = idx >> 4;
    const int ntile = rest % 22;
    const int e     = rest / 22;

    const int cnt = g_cnt[e];
    const int m0  = mtile * BM;
    if (m0 >= cnt) return;
    const int n0  = ntile * 64;

    // wait for this expert's weights
    if (tid == 0) {
        while (*(volatile int*)&g_done[e] < N_PROD) __nanosleep(128);
    }
    __syncthreads();

    extern __shared__ __half smem[];
    const uint32_t sbase = smem_u32(smem);

    const int lane = tid & 31, wid = tid >> 5;
    const int warp_m = wid & 3, warp_n = wid >> 2;

    const int rb = tid >> 3, ch = tid & 7;
    const __half* asrc[4];
    const __half* bsrc[4];
    uint32_t adst[4], bdst[4];
    const int* tokp = g_tok + e * T_TOK;
#pragma unroll
    for (int p = 0; p < 4; ++p) {
        int r = rb + p * 32;
        int m = m0 + r; if (m >= cnt) m = cnt - 1;
        asrc[p] = g_x + (size_t)tokp[m] * H_DIM + ch * 8;
        int grow = (r < 64) ? (n0 + r) : (I_DIM + n0 + r - 64);
        bsrc[p] = g_wgu + ((size_t)e * 2 * I_DIM + grow) * H_DIM + ch * 8;
        adst[p] = (uint32_t)((r * LDSW + ch * 8) * 2);
        bdst[p] = adst[p] + A_OFF_B;
    }

    float accg[2][4][4], accu[2][4][4];
#pragma unroll
    for (int a = 0; a < 2; ++a)
#pragma unroll
        for (int b = 0; b < 4; ++b)
#pragma unroll
            for (int c = 0; c < 4; ++c) { accg[a][b][c] = 0.f; accu[a][b][c] = 0.f; }

    const int arow0 = warp_m * 32 + (lane & 15);
    const int acol  = (lane >> 4) * 8;
    const int brow  = (lane & 7) + ((lane >> 4) << 3);
    const int bcol  = ((lane >> 3) & 1) * 8;

    const int S = H_DIM / BK;   // 32
#pragma unroll
    for (int s = 0; s < 2; ++s) {
        const uint32_t stg = sbase + (uint32_t)(s * STAGE_B);
        const int kb = s * BK;
#pragma unroll
        for (int p = 0; p < 4; ++p) {
            cp16(stg + adst[p], asrc[p] + kb);
            cp16(stg + bdst[p], bsrc[p] + kb);
        }
        CP_COMMIT();
    }

    int buf = 0;
    for (int s = 0; s < S; ++s) {
        CP_WAIT(1);
        __syncthreads();
        if (s + 2 < S) {
            int nb = buf + 2; if (nb >= NSTAGE) nb -= NSTAGE;
            const uint32_t stg = sbase + (uint32_t)(nb * STAGE_B);
            const int kb = (s + 2) * BK;
#pragma unroll
            for (int p = 0; p < 4; ++p) {
                cp16(stg + adst[p], asrc[p] + kb);
                cp16(stg + bdst[p], bsrc[p] + kb);
            }
        }
        CP_COMMIT();

        const uint32_t sa = sbase + (uint32_t)(buf * STAGE_B);
        const uint32_t sb = sa + A_OFF_B;
#pragma unroll
        for (int ks = 0; ks < 4; ++ks) {
            const int kc = ks * 16;
            uint32_t A[2][4], Bg[2][4], Bu[2][4];
            ldm_x4(A[0], sa + (uint32_t)(((arow0     ) * LDSW + kc + acol) * 2));
            ldm_x4(A[1], sa + (uint32_t)(((arow0 + 16) * LDSW + kc + acol) * 2));
#pragma unroll
            for (int bb = 0; bb < 2; ++bb) {
                ldm_x4(Bg[bb], sb + (uint32_t)(((warp_n * 32 + bb * 16 + brow) * LDSW + kc + bcol) * 2));
                ldm_x4(Bu[bb], sb + (uint32_t)(((64 + warp_n * 32 + bb * 16 + brow) * LDSW + kc + bcol) * 2));
            }
#pragma unroll
            for (int mf = 0; mf < 2; ++mf)
#pragma unroll
                for (int nf = 0; nf < 4; ++nf) {
                    mma16816(accg[mf][nf], A[mf], &Bg[nf >> 1][(nf & 1) * 2]);
                    mma16816(accu[mf][nf], A[mf], &Bu[nf >> 1][(nf & 1) * 2]);
                }
        }
        if (++buf == NSTAGE) buf = 0;
    }

#pragma unroll
    for (int mf = 0; mf < 2; ++mf) {
#pragma unroll
        for (int hr = 0; hr < 2; ++hr) {
            const int m = m0 + warp_m * 32 + mf * 16 + (lane >> 2) + hr * 8;
            if (m >= cnt) continue;
            __half* arow = g_act + ((size_t)e * T_TOK + m) * I_DIM;
#pragma unroll
            for (int nf = 0; nf < 4; ++nf) {
                const int c = n0 + warp_n * 32 + nf * 8 + (lane & 3) * 2;
                const float g0 = accg[mf][nf][hr * 2 + 0];
                const float g1 = accg[mf][nf][hr * 2 + 1];
                const float u0 = accu[mf][nf][hr * 2 + 0];
                const float u1 = accu[mf][nf][hr * 2 + 1];
                const float a0 = g0 / (1.0f + __expf(-g0)) * u0;
                const float a1 = g1 / (1.0f + __expf(-g1)) * u1;
                *(__half2*)&arow[c] = __floats2half2_rn(a0, a1);
            }
        }
    }
}

// =================================================================
// GEMM2 (unchanged R14): g_act @ g_wd^T, BM=128, BN=128, BK=64,
// 3-stage cp.async, route-weighted atomicAdd into out.
// =================================================================
__global__ __launch_bounds__(256, 2) void gemm2_kernel(float* __restrict__ out) {
    const int e   = blockIdx.z;
    const int cnt = g_cnt[e];
    const int m0  = blockIdx.x * BM;
    if (m0 >= cnt) return;
    const int n0  = blockIdx.y * 128;

    extern __shared__ __half smem[];
    const uint32_t sbase = smem_u32(smem);

    const int tid = threadIdx.x, lane = tid & 31, wid = tid >> 5;
    const int warp_m = wid & 3, warp_n = wid >> 2;

    const int rb = tid >> 3, ch = tid & 7;
    const __half* asrc[4];
    const __half* bsrc[4];
    uint32_t adst[4], bdst[4];
#pragma unroll
    for (int p = 0; p < 4; ++p) {
        int r = rb + p * 32;
        int m = m0 + r; if (m >= cnt) m = cnt - 1;
        asrc[p] = g_act + ((size_t)e * T_TOK + m) * I_DIM + ch * 8;
        bsrc[p] = g_wd + ((size_t)e * H_DIM + n0 + r) * I_DIM + ch * 8;
        adst[p] = (uint32_t)((r * LDSW + ch * 8) * 2);
        bdst[p] = adst[p] + A_OFF_B;
    }

    float acc[2][8][4];
#pragma unroll
    for (int a = 0; a < 2; ++a)
#pragma unroll
        for (int b = 0; b < 8; ++b)
#pragma unroll
            for (int c = 0; c < 4; ++c) acc[a][b][c] = 0.f;

    const int arow0 = warp_m * 32 + (lane & 15);
    const int acol  = (lane >> 4) * 8;
    const int brow  = (lane & 7) + ((lane >> 4) << 3);
    const int bcol  = ((lane >> 3) & 1) * 8;

    const int S = I_DIM / BK;   // 22
#pragma unroll
    for (int s = 0; s < 2; ++s) {
        const uint32_t stg = sbase + (uint32_t)(s * STAGE_B);
        const int kb = s * BK;
#pragma unroll
        for (int p = 0; p < 4; ++p) {
            cp16(stg + adst[p], asrc[p] + kb);
            cp16(stg + bdst[p], bsrc[p] + kb);
        }
        CP_COMMIT();
    }

    int buf = 0;
    for (int s = 0; s < S; ++s) {
        CP_WAIT(1);
        __syncthreads();
        if (s + 2 < S) {
            int nb = buf + 2; if (nb >= NSTAGE) nb -= NSTAGE;
            const uint32_t stg = sbase + (uint32_t)(nb * STAGE_B);
            const int kb = (s + 2) * BK;
#pragma unroll
            for (int p = 0; p < 4; ++p) {
                cp16(stg + adst[p], asrc[p] + kb);
                cp16(stg + bdst[p], bsrc[p] + kb);
            }
        }
        CP_COMMIT();

        const uint32_t sa = sbase + (uint32_t)(buf * STAGE_B);
        const uint32_t sb = sa + A_OFF_B;
#pragma unroll
        for (int ks = 0; ks < 4; ++ks) {
            const int kc = ks * 16;
            uint32_t A[2][4], B[4][4];
            ldm_x4(A[0], sa + (uint32_t)(((arow0     ) * LDSW + kc + acol) * 2));
            ldm_x4(A[1], sa + (uint32_t)(((arow0 + 16) * LDSW + kc + acol) * 2));
#pragma unroll
            for (int bb = 0; bb < 4; ++bb)
                ldm_x4(B[bb], sb + (uint32_t)(((warp_n * 64 + bb * 16 + brow) * LDSW + kc + bcol) * 2));
#pragma unroll
            for (int mf = 0; mf < 2; ++mf)
#pragma unroll
                for (int nf = 0; nf < 8; ++nf)
                    mma16816(acc[mf][nf], A[mf], &B[nf >> 1][(nf & 1) * 2]);
        }
        if (++buf == NSTAGE) buf = 0;
    }

#pragma unroll
    for (int mf = 0; mf < 2; ++mf) {
#pragma unroll
        for (int hr = 0; hr < 2; ++hr) {
            const int m = m0 + warp_m * 32 + mf * 16 + (lane >> 2) + hr * 8;
            if (m >= cnt) continue;
            const int   tok = g_tok[e * T_TOK + m];
            const float rw  = g_rw [e * T_TOK + m];
            float* orow = out + (size_t)tok * H_DIM;
#pragma unroll
            for (int nf = 0; nf < 8; ++nf) {
                const int c = n0 + warp_n * 64 + nf * 8 + (lane & 3) * 2;
                atomicAdd(&orow[c],     rw * acc[mf][nf][hr * 2 + 0]);
                atomicAdd(&orow[c + 1], rw * acc[mf][nf][hr * 2 + 1]);
            }
        }
    }
}

// ---------------------------------------------------------------
extern "C" void kernel_launch(void* const* d_in, const int* in_sizes, int n_in,
                              void* d_out, int out_size) {
    const float* logits = (const float*)d_in[0];
    const float* x      = (const float*)d_in[1];
    const int*   qgu    = (const int*)  d_in[2];
    const float* sgu    = (const float*)d_in[3];
    const int*   qd     = (const int*)  d_in[4];
    const float* sd     = (const float*)d_in[5];
    float* out = (float*)d_out;

    cudaFuncSetAttribute(fused1_kernel, cudaFuncAttributeMaxDynamicSharedMemorySize, SMEM_BYTES);
    cudaFuncSetAttribute(gemm2_kernel, cudaFuncAttributeMaxDynamicSharedMemorySize, SMEM_BYTES);

    route_kernel<<<1, 1024>>>(logits);

    // producers (128) + gemm1 consumers (16 mtiles x 22 ntiles x 8 experts)
    const int n_blocks = N_PROD + 16 * 22 * NE;   // 2944
    fused1_kernel<<<n_blocks, 256, SMEM_BYTES>>>(x, qgu, sgu, qd, sd, out);

    dim3 g2(T_TOK / BM, H_DIM / 128, NE);         // (16, 16, 8)
    gemm2_kernel<<<g2, 256, SMEM_BYTES>>>(out);
}

// round 17
// speedup vs baseline: 2.0283x; 1.0734x over previous
#include <cuda_runtime.h>
#include <cuda_fp16.h>
#include <stdint.h>
#include <string.h>

#define T_TOK 2048
#define H_DIM 2048
#define I_DIM 1408
#define NE    8
#define GS    128
#define BM    128
#define BK    64
#define LDSW  72                        // smem row stride in halves (144B)
#define A_OFF_B   (128 * LDSW * 2)      // B tile byte offset within a stage
#define STAGE_B   (2 * 128 * LDSW * 2)  // stage bytes (A + B tiles)
#define NSTAGE    3
#define SMEM_BYTES (NSTAGE * STAGE_B)   // 110592 B

// prep grid partition: [route 1 | gate_up dequant 11264 | convert_x 2048]
#define NB_GU   11264
#define NB_X    2048

// ---- persistent device scratch ----
__device__ int    g_cnt[NE];
__device__ int    g_tok[NE * T_TOK];
__device__ float  g_rw [NE * T_TOK];
__device__ __half g_x  [(size_t)T_TOK * H_DIM];
__device__ __half g_act[(size_t)NE * T_TOK * I_DIM];
__device__ __half g_wgu[(size_t)NE * 2 * I_DIM * H_DIM];  // 92 MB fp16
__device__ __half g_wd [(size_t)NE * H_DIM * I_DIM];      // 46 MB fp16

// ---------------- helpers ----------------
__device__ __forceinline__ uint32_t h2u(__half2 h) { uint32_t u; memcpy(&u, &h, 4); return u; }
__device__ __forceinline__ uint32_t smem_u32(const void* p) {
    uint32_t a;
    asm("{ .reg .u64 t; cvta.to.shared.u64 t, %1; cvt.u32.u64 %0, t; }" : "=r"(a) : "l"(p));
    return a;
}
__device__ __forceinline__ void ldm_x4(uint32_t* r, uint32_t addr) {
    asm volatile("ldmatrix.sync.aligned.m8n8.x4.shared.b16 {%0,%1,%2,%3}, [%4];"
        : "=r"(r[0]), "=r"(r[1]), "=r"(r[2]), "=r"(r[3]) : "r"(addr));
}
__device__ __forceinline__ void mma16816(float* d, const uint32_t* a, const uint32_t* b) {
    asm volatile("mma.sync.aligned.m16n8k16.row.col.f32.f16.f16.f32 "
        "{%0,%1,%2,%3}, {%4,%5,%6,%7}, {%8,%9}, {%0,%1,%2,%3};"
        : "+f"(d[0]), "+f"(d[1]), "+f"(d[2]), "+f"(d[3])
        : "r"(a[0]), "r"(a[1]), "r"(a[2]), "r"(a[3]), "r"(b[0]), "r"(b[1]));
}
__device__ __forceinline__ void cp16(uint32_t dst, const void* src) {
    asm volatile("cp.async.cg.shared.global [%0], [%1], 16;" :: "r"(dst), "l"(src));
}
#define CP_COMMIT()  asm volatile("cp.async.commit_group;")
#define CP_WAIT(n)   asm volatile("cp.async.wait_group %0;" :: "n"(n))

// warp-aggregated routed-token push (order-independent downstream)
__device__ __forceinline__ void push_tok(int* scnt, int e, int t, float w) {
    const int lane = threadIdx.x & 31;
    unsigned mask = __match_any_sync(0xffffffffu, e);
    int leader = __ffs(mask) - 1;
    int rank = __popc(mask & ((1u << lane) - 1));
    int base = 0;
    if (lane == leader) base = atomicAdd(&scnt[e], __popc(mask));
    base = __shfl_sync(mask, base, leader);
    int p = base + rank;
    g_tok[e * T_TOK + p] = t;
    g_rw [e * T_TOK + p] = w;
}

// ---------------- L0 (fused into prep): route | gate_up dequant | convert_x ----------------
__global__ void prep_kernel(const int* __restrict__ q, const float* __restrict__ s,
                            const float* __restrict__ x,
                            const float* __restrict__ logits) {
    const int bid = blockIdx.x;
    const int tid = threadIdx.x;

    if (bid == 0) {
        // ---- routing: one 256-thread block, warp-aggregated atomics ----
        __shared__ int scnt[NE];
        if (tid < NE) scnt[tid] = 0;
        __syncthreads();
        for (int t0 = 0; t0 < T_TOK; t0 += 256) {
            const int t = t0 + tid;
            float v[NE];
#pragma unroll
            for (int e = 0; e < NE; ++e) v[e] = logits[t * NE + e];
            int i0 = 0;
#pragma unroll
            for (int e = 1; e < NE; ++e) if (v[e] > v[i0]) i0 = e;
            int i1 = (i0 == 0) ? 1 : 0;
#pragma unroll
            for (int e = 0; e < NE; ++e) if (e != i0 && v[e] > v[i1]) i1 = e;
            float ex = __expf(v[i1] - v[i0]);
            float w0 = 1.0f / (1.0f + ex);
            float w1 = ex * w0;
            push_tok(scnt, i0, t, w0);
            push_tok(scnt, i1, t, w1);
        }
        __syncthreads();
        if (tid < NE) g_cnt[tid] = scnt[tid];
        return;
    }

    const int wb = bid - 1;
    if (wb < NB_GU) {
        // ---- gate_up dequant ----
        int gid = wb * 256 + tid;
        int row = gid >> 7;
        int kc  = (gid & 127) << 4;
        const int4* src = (const int4*)(q + (size_t)row * H_DIM + kc);
        float sc = s[row * (H_DIM / GS) + (kc >> 7)];
        uint32_t o[8];
#pragma unroll
        for (int j = 0; j < 4; ++j) {
            int4 v = src[j];
            o[j * 2 + 0] = h2u(__floats2half2_rn(sc * (float)(v.x - 8), sc * (float)(v.y - 8)));
            o[j * 2 + 1] = h2u(__floats2half2_rn(sc * (float)(v.z - 8), sc * (float)(v.w - 8)));
        }
        uint4* dst = (uint4*)(g_wgu + (size_t)row * H_DIM + kc);
        dst[0] = make_uint4(o[0], o[1], o[2], o[3]);
        dst[1] = make_uint4(o[4], o[5], o[6], o[7]);
    } else {
        // ---- convert_x ----
        size_t i = ((size_t)(wb - NB_GU) * 256 + tid) * 8;
        float4 a = *(const float4*)(x + i);
        float4 b = *(const float4*)(x + i + 4);
        uint4 o;
        o.x = h2u(__floats2half2_rn(a.x, a.y));
        o.y = h2u(__floats2half2_rn(a.z, a.w));
        o.z = h2u(__floats2half2_rn(b.x, b.y));
        o.w = h2u(__floats2half2_rn(b.z, b.w));
        *(uint4*)(g_x + i) = o;
    }
}

// =================================================================
// GEMM1 (R14 core) + hidden y==0 slice: dn-dequant THEN out-zeroing.
// GEMM: g_x @ g_wgu^T, fused SwiGLU -> g_act.
// BM=128, BN=64 gate + 64 up, BK=64, 3-stage cp.async.
// grid (16, 23, 8): y==0 slice (128 CTAs), y-1 in [0,22) gemm ntile.
// =================================================================
__global__ __launch_bounds__(256, 2) void gemm1_kernel(
    const int* __restrict__ qd, const float* __restrict__ sd,
    float* __restrict__ out)
{
    const int e = blockIdx.z;

    if (blockIdx.y == 0) {
        const int cta = blockIdx.z * 16 + blockIdx.x;           // 0..127
        const int nthreads = 128 * 256;
        // ---- dn dequant: 1441792 chunks of 16 ints ----
        const int total = NE * H_DIM * (I_DIM / 16);
        for (int gid = cta * 256 + threadIdx.x; gid < total; gid += nthreads) {
            int row = gid / 88;
            int kc  = (gid - row * 88) << 4;
            const int4* src = (const int4*)(qd + (size_t)row * I_DIM + kc);
            float sc = sd[row * (I_DIM / GS) + (kc >> 7)];
            uint32_t o[8];
#pragma unroll
            for (int j = 0; j < 4; ++j) {
                int4 v = src[j];
                o[j * 2 + 0] = h2u(__floats2half2_rn(sc * (float)(v.x - 8), sc * (float)(v.y - 8)));
                o[j * 2 + 1] = h2u(__floats2half2_rn(sc * (float)(v.z - 8), sc * (float)(v.w - 8)));
            }
            uint4* dst = (uint4*)(g_wd + (size_t)row * I_DIM + kc);
            dst[0] = make_uint4(o[0], o[1], o[2], o[3]);
            dst[1] = make_uint4(o[4], o[5], o[6], o[7]);
        }
        // ---- zero out: 1M float4 ----
        const int ztot = T_TOK * H_DIM / 4;
        for (int gid = cta * 256 + threadIdx.x; gid < ztot; gid += nthreads)
            *(float4*)(out + (size_t)gid * 4) = make_float4(0.f, 0.f, 0.f, 0.f);
        return;
    }

    const int cnt = g_cnt[e];
    const int m0  = blockIdx.x * BM;
    if (m0 >= cnt) return;
    const int n0  = (blockIdx.y - 1) * 64;

    extern __shared__ __half smem[];
    const uint32_t sbase = smem_u32(smem);

    const int tid = threadIdx.x, lane = tid & 31, wid = tid >> 5;
    const int warp_m = wid & 3, warp_n = wid >> 2;

    const int rb = tid >> 3, ch = tid & 7;
    const __half* asrc[4];
    const __half* bsrc[4];
    uint32_t adst[4], bdst[4];
    const int* tokp = g_tok + e * T_TOK;
#pragma unroll
    for (int p = 0; p < 4; ++p) {
        int r = rb + p * 32;
        int m = m0 + r; if (m >= cnt) m = cnt - 1;
        asrc[p] = g_x + (size_t)tokp[m] * H_DIM + ch * 8;
        int grow = (r < 64) ? (n0 + r) : (I_DIM + n0 + r - 64);
        bsrc[p] = g_wgu + ((size_t)e * 2 * I_DIM + grow) * H_DIM + ch * 8;
        adst[p] = (uint32_t)((r * LDSW + ch * 8) * 2);
        bdst[p] = adst[p] + A_OFF_B;
    }

    float accg[2][4][4], accu[2][4][4];
#pragma unroll
    for (int a = 0; a < 2; ++a)
#pragma unroll
        for (int b = 0; b < 4; ++b)
#pragma unroll
            for (int c = 0; c < 4; ++c) { accg[a][b][c] = 0.f; accu[a][b][c] = 0.f; }

    const int arow0 = warp_m * 32 + (lane & 15);
    const int acol  = (lane >> 4) * 8;
    const int brow  = (lane & 7) + ((lane >> 4) << 3);
    const int bcol  = ((lane >> 3) & 1) * 8;

    const int S = H_DIM / BK;   // 32
#pragma unroll
    for (int s = 0; s < 2; ++s) {
        const uint32_t stg = sbase + (uint32_t)(s * STAGE_B);
        const int kb = s * BK;
#pragma unroll
        for (int p = 0; p < 4; ++p) {
            cp16(stg + adst[p], asrc[p] + kb);
            cp16(stg + bdst[p], bsrc[p] + kb);
        }
        CP_COMMIT();
    }

    int buf = 0;
    for (int s = 0; s < S; ++s) {
        CP_WAIT(1);
        __syncthreads();
        if (s + 2 < S) {
            int nb = buf + 2; if (nb >= NSTAGE) nb -= NSTAGE;
            const uint32_t stg = sbase + (uint32_t)(nb * STAGE_B);
            const int kb = (s + 2) * BK;
#pragma unroll
            for (int p = 0; p < 4; ++p) {
                cp16(stg + adst[p], asrc[p] + kb);
                cp16(stg + bdst[p], bsrc[p] + kb);
            }
        }
        CP_COMMIT();

        const uint32_t sa = sbase + (uint32_t)(buf * STAGE_B);
        const uint32_t sb = sa + A_OFF_B;
#pragma unroll
        for (int ks = 0; ks < 4; ++ks) {
            const int kc = ks * 16;
            uint32_t A[2][4], Bg[2][4], Bu[2][4];
            ldm_x4(A[0], sa + (uint32_t)(((arow0     ) * LDSW + kc + acol) * 2));
            ldm_x4(A[1], sa + (uint32_t)(((arow0 + 16) * LDSW + kc + acol) * 2));
#pragma unroll
            for (int bb = 0; bb < 2; ++bb) {
                ldm_x4(Bg[bb], sb + (uint32_t)(((warp_n * 32 + bb * 16 + brow) * LDSW + kc + bcol) * 2));
                ldm_x4(Bu[bb], sb + (uint32_t)(((64 + warp_n * 32 + bb * 16 + brow) * LDSW + kc + bcol) * 2));
            }
#pragma unroll
            for (int mf = 0; mf < 2; ++mf)
#pragma unroll
                for (int nf = 0; nf < 4; ++nf) {
                    mma16816(accg[mf][nf], A[mf], &Bg[nf >> 1][(nf & 1) * 2]);
                    mma16816(accu[mf][nf], A[mf], &Bu[nf >> 1][(nf & 1) * 2]);
                }
        }
        if (++buf == NSTAGE) buf = 0;
    }

#pragma unroll
    for (int mf = 0; mf < 2; ++mf) {
#pragma unroll
        for (int hr = 0; hr < 2; ++hr) {
            const int m = m0 + warp_m * 32 + mf * 16 + (lane >> 2) + hr * 8;
            if (m >= cnt) continue;
            __half* arow = g_act + ((size_t)e * T_TOK + m) * I_DIM;
#pragma unroll
            for (int nf = 0; nf < 4; ++nf) {
                const int c = n0 + warp_n * 32 + nf * 8 + (lane & 3) * 2;
                const float g0 = accg[mf][nf][hr * 2 + 0];
                const float g1 = accg[mf][nf][hr * 2 + 1];
                const float u0 = accu[mf][nf][hr * 2 + 0];
                const float u1 = accu[mf][nf][hr * 2 + 1];
                const float a0 = g0 / (1.0f + __expf(-g0)) * u0;
                const float a1 = g1 / (1.0f + __expf(-g1)) * u1;
                *(__half2*)&arow[c] = __floats2half2_rn(a0, a1);
            }
        }
    }
}

// =================================================================
// GEMM2 (unchanged R14): g_act @ g_wd^T, BM=128, BN=128, BK=64,
// 3-stage cp.async, route-weighted atomicAdd into out.
// =================================================================
__global__ __launch_bounds__(256, 2) void gemm2_kernel(float* __restrict__ out) {
    const int e   = blockIdx.z;
    const int cnt = g_cnt[e];
    const int m0  = blockIdx.x * BM;
    if (m0 >= cnt) return;
    const int n0  = blockIdx.y * 128;

    extern __shared__ __half smem[];
    const uint32_t sbase = smem_u32(smem);

    const int tid = threadIdx.x, lane = tid & 31, wid = tid >> 5;
    const int warp_m = wid & 3, warp_n = wid >> 2;

    const int rb = tid >> 3, ch = tid & 7;
    const __half* asrc[4];
    const __half* bsrc[4];
    uint32_t adst[4], bdst[4];
#pragma unroll
    for (int p = 0; p < 4; ++p) {
        int r = rb + p * 32;
        int m = m0 + r; if (m >= cnt) m = cnt - 1;
        asrc[p] = g_act + ((size_t)e * T_TOK + m) * I_DIM + ch * 8;
        bsrc[p] = g_wd + ((size_t)e * H_DIM + n0 + r) * I_DIM + ch * 8;
        adst[p] = (uint32_t)((r * LDSW + ch * 8) * 2);
        bdst[p] = adst[p] + A_OFF_B;
    }

    float acc[2][8][4];
#pragma unroll
    for (int a = 0; a < 2; ++a)
#pragma unroll
        for (int b = 0; b < 8; ++b)
#pragma unroll
            for (int c = 0; c < 4; ++c) acc[a][b][c] = 0.f;

    const int arow0 = warp_m * 32 + (lane & 15);
    const int acol  = (lane >> 4) * 8;
    const int brow  = (lane & 7) + ((lane >> 4) << 3);
    const int bcol  = ((lane >> 3) & 1) * 8;

    const int S = I_DIM / BK;   // 22
#pragma unroll
    for (int s = 0; s < 2; ++s) {
        const uint32_t stg = sbase + (uint32_t)(s * STAGE_B);
        const int kb = s * BK;
#pragma unroll
        for (int p = 0; p < 4; ++p) {
            cp16(stg + adst[p], asrc[p] + kb);
            cp16(stg + bdst[p], bsrc[p] + kb);
        }
        CP_COMMIT();
    }

    int buf = 0;
    for (int s = 0; s < S; ++s) {
        CP_WAIT(1);
        __syncthreads();
        if (s + 2 < S) {
            int nb = buf + 2; if (nb >= NSTAGE) nb -= NSTAGE;
            const uint32_t stg = sbase + (uint32_t)(nb * STAGE_B);
            const int kb = (s + 2) * BK;
#pragma unroll
            for (int p = 0; p < 4; ++p) {
                cp16(stg + adst[p], asrc[p] + kb);
                cp16(stg + bdst[p], bsrc[p] + kb);
            }
        }
        CP_COMMIT();

        const uint32_t sa = sbase + (uint32_t)(buf * STAGE_B);
        const uint32_t sb = sa + A_OFF_B;
#pragma unroll
        for (int ks = 0; ks < 4; ++ks) {
            const int kc = ks * 16;
            uint32_t A[2][4], B[4][4];
            ldm_x4(A[0], sa + (uint32_t)(((arow0     ) * LDSW + kc + acol) * 2));
            ldm_x4(A[1], sa + (uint32_t)(((arow0 + 16) * LDSW + kc + acol) * 2));
#pragma unroll
            for (int bb = 0; bb < 4; ++bb)
                ldm_x4(B[bb], sb + (uint32_t)(((warp_n * 64 + bb * 16 + brow) * LDSW + kc + bcol) * 2));
#pragma unroll
            for (int mf = 0; mf < 2; ++mf)
#pragma unroll
                for (int nf = 0; nf < 8; ++nf)
                    mma16816(acc[mf][nf], A[mf], &B[nf >> 1][(nf & 1) * 2]);
        }
        if (++buf == NSTAGE) buf = 0;
    }

#pragma unroll
    for (int mf = 0; mf < 2; ++mf) {
#pragma unroll
        for (int hr = 0; hr < 2; ++hr) {
            const int m = m0 + warp_m * 32 + mf * 16 + (lane >> 2) + hr * 8;
            if (m >= cnt) continue;
            const int   tok = g_tok[e * T_TOK + m];
            const float rw  = g_rw [e * T_TOK + m];
            float* orow = out + (size_t)tok * H_DIM;
#pragma unroll
            for (int nf = 0; nf < 8; ++nf) {
                const int c = n0 + warp_n * 64 + nf * 8 + (lane & 3) * 2;
                atomicAdd(&orow[c],     rw * acc[mf][nf][hr * 2 + 0]);
                atomicAdd(&orow[c + 1], rw * acc[mf][nf][hr * 2 + 1]);
            }
        }
    }
}

// ---------------------------------------------------------------
extern "C" void kernel_launch(void* const* d_in, const int* in_sizes, int n_in,
                              void* d_out, int out_size) {
    const float* logits = (const float*)d_in[0];
    const float* x      = (const float*)d_in[1];
    const int*   qgu    = (const int*)  d_in[2];
    const float* sgu    = (const float*)d_in[3];
    const int*   qd     = (const int*)  d_in[4];
    const float* sd     = (const float*)d_in[5];
    float* out = (float*)d_out;

    cudaFuncSetAttribute(gemm1_kernel, cudaFuncAttributeMaxDynamicSharedMemorySize, SMEM_BYTES);
    cudaFuncSetAttribute(gemm2_kernel, cudaFuncAttributeMaxDynamicSharedMemorySize, SMEM_BYTES);

    // prep: [route | gate_up dequant | convert_x] in ONE launch
    prep_kernel<<<1 + NB_GU + NB_X, 256>>>(qgu, sgu, x, logits);

    dim3 g1(T_TOK / BM, I_DIM / 64 + 1, NE);   // (16, 23, 8): y==0 = dn-dequant + zero slice
    gemm1_kernel<<<g1, 256, SMEM_BYTES>>>(qd, sd, out);

    dim3 g2(T_TOK / BM, H_DIM / 128, NE);      // (16, 16, 8)
    gemm2_kernel<<<g2, 256, SMEM_BYTES>>>(out);
}